// round 5
// baseline (speedup 1.0000x reference)
#include <cuda_runtime.h>
#include <cuda_bf16.h>

// Problem shape (fixed by setup_inputs): T=32, B=256, C_in=C_out=4096.
#define T_STEPS 32
#define BATCH   256
#define C_IN    4096
#define C_OUT   4096
#define M_DIM   (T_STEPS * BATCH)   // 8192 GEMM rows

// Scratch for pre-activation currents: [T*B, C_OUT] fp32 = 128 MB.
__device__ float g_current[(size_t)M_DIM * C_OUT];

// ---------------------------------------------------------------------------
// High-accuracy GEMM (NT): C[m][n] = sum_k A[m][k]*W[n][k] + bias[n]
// Tile 128x64x32, 256 threads, 8x4 micro-tile.
// Accuracy scheme: per-k0-slab local accumulator `blk` (32 sequential terms,
// error ~sqrt(32)*eps), Kahan-compensated merge into `acc` (no growth across
// the 128 slabs). Total error ~1-2 ulp vs ~64 ulp for naive sequential sum.
// ---------------------------------------------------------------------------
#define BM 128
#define BN 64
#define BK 32
#define TM 8
#define TN 4

__global__ __launch_bounds__(256, 2)
void gemm_nt_bias_kahan_kernel(const float* __restrict__ A,
                               const float* __restrict__ W,
                               const float* __restrict__ bias,
                               float* __restrict__ C)
{
    __shared__ float As[BK][BM];   // As[k][m]  (16 KB)
    __shared__ float Bs[BK][BN];   // Bs[k][n]  ( 8 KB)

    const int K  = C_IN;
    const int m0 = blockIdx.y * BM;
    const int n0 = blockIdx.x * BN;

    const int tid = threadIdx.x;
    const int tx  = tid & 15;      // 16 thread-cols * TN=4  -> 64
    const int ty  = tid >> 4;      // 16 thread-rows * TM=8  -> 128

    float acc[TM][TN];
    float cmp[TM][TN];
#pragma unroll
    for (int i = 0; i < TM; i++)
#pragma unroll
        for (int j = 0; j < TN; j++) { acc[i][j] = 0.0f; cmp[i][j] = 0.0f; }

    // A tile: 128 rows x 32 cols = 1024 float4 slots (8 quads/row), 4/thread.
    // B tile:  64 rows x 32 cols =  512 float4 slots (8 quads/row), 2/thread.
    for (int k0 = 0; k0 < K; k0 += BK) {
#pragma unroll
        for (int i = 0; i < 4; i++) {
            const int s   = tid * 4 + i;
            const int row = s >> 3;
            const int q   = s & 7;
            const float4 v = *reinterpret_cast<const float4*>(
                A + (size_t)(m0 + row) * K + k0 + q * 4);
            As[q * 4 + 0][row] = v.x;
            As[q * 4 + 1][row] = v.y;
            As[q * 4 + 2][row] = v.z;
            As[q * 4 + 3][row] = v.w;
        }
#pragma unroll
        for (int i = 0; i < 2; i++) {
            const int s   = tid * 2 + i;
            const int row = s >> 3;
            const int q   = s & 7;
            const float4 v = *reinterpret_cast<const float4*>(
                W + (size_t)(n0 + row) * K + k0 + q * 4);
            Bs[q * 4 + 0][row] = v.x;
            Bs[q * 4 + 1][row] = v.y;
            Bs[q * 4 + 2][row] = v.z;
            Bs[q * 4 + 3][row] = v.w;
        }
        __syncthreads();

        // Fresh slab accumulator.
        float blk[TM][TN];
#pragma unroll
        for (int i = 0; i < TM; i++)
#pragma unroll
            for (int j = 0; j < TN; j++) blk[i][j] = 0.0f;

#pragma unroll
        for (int kk = 0; kk < BK; kk++) {
            float a[TM], b[TN];
#pragma unroll
            for (int i = 0; i < TM; i += 4) {
                const float4 v = *reinterpret_cast<const float4*>(&As[kk][ty * TM + i]);
                a[i + 0] = v.x; a[i + 1] = v.y; a[i + 2] = v.z; a[i + 3] = v.w;
            }
            {
                const float4 v = *reinterpret_cast<const float4*>(&Bs[kk][tx * TN]);
                b[0] = v.x; b[1] = v.y; b[2] = v.z; b[3] = v.w;
            }
#pragma unroll
            for (int i = 0; i < TM; i++)
#pragma unroll
                for (int j = 0; j < TN; j++)
                    blk[i][j] = fmaf(a[i], b[j], blk[i][j]);
        }

        // Kahan merge: acc += blk with compensation cmp.
#pragma unroll
        for (int i = 0; i < TM; i++)
#pragma unroll
            for (int j = 0; j < TN; j++) {
                const float y = __fsub_rn(blk[i][j], cmp[i][j]);
                const float t = __fadd_rn(acc[i][j], y);
                cmp[i][j]     = __fsub_rn(__fsub_rn(t, acc[i][j]), y);
                acc[i][j]     = t;
            }
        __syncthreads();
    }

    // Epilogue: fold in compensation residual, add bias, store fp32.
#pragma unroll
    for (int i = 0; i < TM; i++) {
        const int m = m0 + ty * TM + i;
        const int n = n0 + tx * TN;
        float4 v;
        v.x = __fsub_rn(acc[i][0], cmp[i][0]) + bias[n + 0];
        v.y = __fsub_rn(acc[i][1], cmp[i][1]) + bias[n + 1];
        v.z = __fsub_rn(acc[i][2], cmp[i][2]) + bias[n + 2];
        v.w = __fsub_rn(acc[i][3], cmp[i][3]) + bias[n + 3];
        *reinterpret_cast<float4*>(C + (size_t)m * C_OUT + n) = v;
    }
}

// ---------------------------------------------------------------------------
// LIF scan: one thread per (b, c_out) neuron, 32 sequential timesteps.
// UNFUSED mul/add to match XLA's elementwise emission (no fp contraction):
//   mem = fmul(d, mem) fadd current; s = (mem - th) > 0; mem = mem - s*th.
// ---------------------------------------------------------------------------
__global__ __launch_bounds__(256)
void lif_scan_kernel(const float* __restrict__ cur,
                     float* __restrict__ out,
                     const float* __restrict__ decay,
                     const float* __restrict__ thresh)
{
    const int i = blockIdx.x * blockDim.x + threadIdx.x;  // 0 .. B*C_OUT-1
    const float d  = decay[0];
    const float th = thresh[0];
    const size_t stride = (size_t)BATCH * C_OUT;

    float mem = 0.0f;
#pragma unroll
    for (int t = 0; t < T_STEPS; t++) {
        const size_t idx = (size_t)t * stride + i;
        const float c = cur[idx];
        mem = __fadd_rn(__fmul_rn(d, mem), c);          // unfused LI step
        const float v = __fsub_rn(mem, th);
        const float s = (v > 0.0f) ? 1.0f : 0.0f;
        out[idx] = s;
        mem = __fsub_rn(mem, __fmul_rn(s, th));         // reset by subtraction
    }
}

// ---------------------------------------------------------------------------
// Launch: inputs in metadata order: x, W, b, decay, thresh.
// ---------------------------------------------------------------------------
extern "C" void kernel_launch(void* const* d_in, const int* in_sizes, int n_in,
                              void* d_out, int out_size)
{
    const float* x      = (const float*)d_in[0];  // [T, B, C_IN]
    const float* W      = (const float*)d_in[1];  // [C_OUT, C_IN]
    const float* bias   = (const float*)d_in[2];  // [C_OUT]
    const float* decay  = (const float*)d_in[3];  // [1]
    const float* thresh = (const float*)d_in[4];  // [1]
    float* out = (float*)d_out;                   // [T, B, C_OUT]

    float* cur = nullptr;
    cudaGetSymbolAddress((void**)&cur, g_current);

    dim3 gblock(256);
    dim3 ggrid(C_OUT / BN, M_DIM / BM);   // (64, 64)
    gemm_nt_bias_kahan_kernel<<<ggrid, gblock>>>(x, W, bias, cur);

    const int neurons = BATCH * C_OUT;    // 1,048,576
    lif_scan_kernel<<<neurons / 256, 256>>>(cur, out, decay, thresh);
}

// round 6
// speedup vs baseline: 1.0608x; 1.0608x over previous
#include <cuda_runtime.h>
#include <cuda_bf16.h>

// Problem shape (fixed by setup_inputs): T=32, B=256, C_in=C_out=4096.
#define T_STEPS 32
#define BATCH   256
#define C_IN    4096
#define C_OUT   4096
#define M_DIM   (T_STEPS * BATCH)   // 8192 GEMM rows

// Scratch for pre-activation currents: [T*B, C_OUT] fp32 = 128 MB.
__device__ float g_current[(size_t)M_DIM * C_OUT];

typedef unsigned long long ull;

// Packed f32x2 ops (SASS FFMA2 path — 2x fp32 throughput vs FFMA-3reg on
// sm_103a). Per-component rounding identical to scalar __fmaf_rn/__fadd_rn,
// so results stay bit-identical to the scalar R5 kernel.
__device__ __forceinline__ ull fma2(ull a, ull b, ull c) {
    ull d;
    asm("fma.rn.f32x2 %0, %1, %2, %3;" : "=l"(d) : "l"(a), "l"(b), "l"(c));
    return d;
}
__device__ __forceinline__ ull add2(ull a, ull b) {
    ull d;
    asm("add.rn.f32x2 %0, %1, %2;" : "=l"(d) : "l"(a), "l"(b));
    return d;
}
__device__ __forceinline__ ull pack2(float lo, float hi) {
    ull d;
    asm("mov.b64 %0, {%1, %2};" : "=l"(d) : "f"(lo), "f"(hi));
    return d;
}
__device__ __forceinline__ void unpack2(ull v, float& lo, float& hi) {
    asm("mov.b64 {%0, %1}, %2;" : "=f"(lo), "=f"(hi) : "l"(v));
}

// ---------------------------------------------------------------------------
// GEMM (NT): C[m][n] = sum_k A[m][k]*W[n][k] + bias[n]
// Tile 128x64x32, 256 threads, 8x4 micro-tile, accumulators packed f32x2
// along M. Per-slab fresh accumulator + packed-Kahan merge: identical
// arithmetic sequence per output element to the R5 scalar kernel.
// Double-buffered SMEM + register-staged global prefetch.
// ---------------------------------------------------------------------------
#define BM 128
#define BN 64
#define BK 32
#define TM 8
#define TN 4

__global__ __launch_bounds__(256, 1)
void gemm_nt_bias_kahan_f32x2_kernel(const float* __restrict__ A,
                                     const float* __restrict__ W,
                                     const float* __restrict__ bias,
                                     float* __restrict__ C)
{
    __shared__ float As[2][BK][BM];   // As[buf][k][m]  (2 x 16 KB)
    __shared__ float Bs[2][BK][BN];   // Bs[buf][k][n]  (2 x  8 KB)

    const int K  = C_IN;
    const int m0 = blockIdx.y * BM;
    const int n0 = blockIdx.x * BN;

    const int tid = threadIdx.x;
    const int tx  = tid & 15;      // 16 thread-cols * TN=4  -> 64
    const int ty  = tid >> 4;      // 16 thread-rows * TM=8  -> 128

    // Packed accumulators: [pair-of-m][n], pair ip covers rows (2ip, 2ip+1).
    ull acc[TM / 2][TN];
    ull cmp[TM / 2][TN];
#pragma unroll
    for (int ip = 0; ip < TM / 2; ip++)
#pragma unroll
        for (int j = 0; j < TN; j++) { acc[ip][j] = 0ull; cmp[ip][j] = 0ull; }

    const ull negone = pack2(-1.0f, -1.0f);

    // ---- global load (registers) + shared store helpers, same slot plan as R5
    float4 rA[4], rB[2];

    auto ldg_slab = [&](int k0) {
#pragma unroll
        for (int i = 0; i < 4; i++) {
            const int s   = tid * 4 + i;
            const int row = s >> 3;
            const int q   = s & 7;
            rA[i] = *reinterpret_cast<const float4*>(
                A + (size_t)(m0 + row) * K + k0 + q * 4);
        }
#pragma unroll
        for (int i = 0; i < 2; i++) {
            const int s   = tid * 2 + i;
            const int row = s >> 3;
            const int q   = s & 7;
            rB[i] = *reinterpret_cast<const float4*>(
                W + (size_t)(n0 + row) * K + k0 + q * 4);
        }
    };
    auto sts_slab = [&](int buf) {
#pragma unroll
        for (int i = 0; i < 4; i++) {
            const int s   = tid * 4 + i;
            const int row = s >> 3;
            const int q   = s & 7;
            As[buf][q * 4 + 0][row] = rA[i].x;
            As[buf][q * 4 + 1][row] = rA[i].y;
            As[buf][q * 4 + 2][row] = rA[i].z;
            As[buf][q * 4 + 3][row] = rA[i].w;
        }
#pragma unroll
        for (int i = 0; i < 2; i++) {
            const int s   = tid * 2 + i;
            const int row = s >> 3;
            const int q   = s & 7;
            Bs[buf][q * 4 + 0][row] = rB[i].x;
            Bs[buf][q * 4 + 1][row] = rB[i].y;
            Bs[buf][q * 4 + 2][row] = rB[i].z;
            Bs[buf][q * 4 + 3][row] = rB[i].w;
        }
    };

    // Prologue: stage slab 0.
    ldg_slab(0);
    sts_slab(0);
    __syncthreads();

    int buf = 0;
    for (int k0 = 0; k0 < K; k0 += BK) {
        const bool has_next = (k0 + BK) < K;
        if (has_next) ldg_slab(k0 + BK);   // prefetch next slab into registers

        // Fresh packed slab accumulator.
        ull blk[TM / 2][TN];
#pragma unroll
        for (int ip = 0; ip < TM / 2; ip++)
#pragma unroll
            for (int j = 0; j < TN; j++) blk[ip][j] = 0ull;

#pragma unroll
        for (int kk = 0; kk < BK; kk++) {
            // A fragment: rows ty*8 .. ty*8+7 as 4 natural f32x2 pairs.
            const ulonglong2 av0 =
                *reinterpret_cast<const ulonglong2*>(&As[buf][kk][ty * TM]);
            const ulonglong2 av1 =
                *reinterpret_cast<const ulonglong2*>(&As[buf][kk][ty * TM + 4]);
            ull ap[4];
            ap[0] = av0.x; ap[1] = av0.y; ap[2] = av1.x; ap[3] = av1.y;

            // B fragment: 4 scalars, duplicated into packed lanes.
            const float4 bv =
                *reinterpret_cast<const float4*>(&Bs[buf][kk][tx * TN]);
            ull bd[4];
            bd[0] = pack2(bv.x, bv.x);
            bd[1] = pack2(bv.y, bv.y);
            bd[2] = pack2(bv.z, bv.z);
            bd[3] = pack2(bv.w, bv.w);

#pragma unroll
            for (int ip = 0; ip < TM / 2; ip++)
#pragma unroll
                for (int j = 0; j < TN; j++)
                    blk[ip][j] = fma2(ap[ip], bd[j], blk[ip][j]);
        }

        // Packed Kahan merge (exact component-wise match of scalar version):
        //   y = blk - cmp; t = acc + y; cmp = (t - acc) - y; acc = t.
#pragma unroll
        for (int ip = 0; ip < TM / 2; ip++)
#pragma unroll
            for (int j = 0; j < TN; j++) {
                const ull y = fma2(cmp[ip][j], negone, blk[ip][j]); // blk - cmp
                const ull t = add2(acc[ip][j], y);                  // acc + y
                const ull d = fma2(acc[ip][j], negone, t);          // t - acc
                cmp[ip][j]  = fma2(y, negone, d);                   // d - y
                acc[ip][j]  = t;
            }

        if (has_next) {
            sts_slab(buf ^ 1);   // fill the idle buffer
            __syncthreads();
            buf ^= 1;
        }
    }

    // Epilogue: fold compensation, add bias, store fp32 (same exprs as R5).
#pragma unroll
    for (int ip = 0; ip < TM / 2; ip++) {
        float a_lo[TN], a_hi[TN], c_lo[TN], c_hi[TN];
#pragma unroll
        for (int j = 0; j < TN; j++) {
            unpack2(acc[ip][j], a_lo[j], a_hi[j]);
            unpack2(cmp[ip][j], c_lo[j], c_hi[j]);
        }
        const int n = n0 + tx * TN;
        {
            const int m = m0 + ty * TM + 2 * ip;
            float4 v;
            v.x = __fsub_rn(a_lo[0], c_lo[0]) + bias[n + 0];
            v.y = __fsub_rn(a_lo[1], c_lo[1]) + bias[n + 1];
            v.z = __fsub_rn(a_lo[2], c_lo[2]) + bias[n + 2];
            v.w = __fsub_rn(a_lo[3], c_lo[3]) + bias[n + 3];
            *reinterpret_cast<float4*>(C + (size_t)m * C_OUT + n) = v;
        }
        {
            const int m = m0 + ty * TM + 2 * ip + 1;
            float4 v;
            v.x = __fsub_rn(a_hi[0], c_hi[0]) + bias[n + 0];
            v.y = __fsub_rn(a_hi[1], c_hi[1]) + bias[n + 1];
            v.z = __fsub_rn(a_hi[2], c_hi[2]) + bias[n + 2];
            v.w = __fsub_rn(a_hi[3], c_hi[3]) + bias[n + 3];
            *reinterpret_cast<float4*>(C + (size_t)m * C_OUT + n) = v;
        }
    }
}

// ---------------------------------------------------------------------------
// LIF scan: one thread per 4 adjacent (b, c_out) neurons, 32 sequential
// timesteps. Per-element math identical (unfused mul/add) to R5; float4
// vectorization only changes the memory access width.
// ---------------------------------------------------------------------------
__global__ __launch_bounds__(256)
void lif_scan_kernel(const float4* __restrict__ cur,
                     float4* __restrict__ out,
                     const float* __restrict__ decay,
                     const float* __restrict__ thresh)
{
    const int i = blockIdx.x * blockDim.x + threadIdx.x;  // 0 .. B*C_OUT/4-1
    const float d  = decay[0];
    const float th = thresh[0];
    const size_t stride = (size_t)BATCH * C_OUT / 4;

    float m0 = 0.0f, m1 = 0.0f, m2 = 0.0f, m3 = 0.0f;
#pragma unroll
    for (int t = 0; t < T_STEPS; t++) {
        const size_t idx = (size_t)t * stride + i;
        const float4 c = cur[idx];
        float4 s;
        m0 = __fadd_rn(__fmul_rn(d, m0), c.x);
        m1 = __fadd_rn(__fmul_rn(d, m1), c.y);
        m2 = __fadd_rn(__fmul_rn(d, m2), c.z);
        m3 = __fadd_rn(__fmul_rn(d, m3), c.w);
        s.x = (__fsub_rn(m0, th) > 0.0f) ? 1.0f : 0.0f;
        s.y = (__fsub_rn(m1, th) > 0.0f) ? 1.0f : 0.0f;
        s.z = (__fsub_rn(m2, th) > 0.0f) ? 1.0f : 0.0f;
        s.w = (__fsub_rn(m3, th) > 0.0f) ? 1.0f : 0.0f;
        out[idx] = s;
        m0 = __fsub_rn(m0, __fmul_rn(s.x, th));
        m1 = __fsub_rn(m1, __fmul_rn(s.y, th));
        m2 = __fsub_rn(m2, __fmul_rn(s.z, th));
        m3 = __fsub_rn(m3, __fmul_rn(s.w, th));
    }
}

// ---------------------------------------------------------------------------
// Launch: inputs in metadata order: x, W, b, decay, thresh.
// ---------------------------------------------------------------------------
extern "C" void kernel_launch(void* const* d_in, const int* in_sizes, int n_in,
                              void* d_out, int out_size)
{
    const float* x      = (const float*)d_in[0];  // [T, B, C_IN]
    const float* W      = (const float*)d_in[1];  // [C_OUT, C_IN]
    const float* bias   = (const float*)d_in[2];  // [C_OUT]
    const float* decay  = (const float*)d_in[3];  // [1]
    const float* thresh = (const float*)d_in[4];  // [1]
    float* out = (float*)d_out;                   // [T, B, C_OUT]

    float* cur = nullptr;
    cudaGetSymbolAddress((void**)&cur, g_current);

    dim3 gblock(256);
    dim3 ggrid(C_OUT / BN, M_DIM / BM);   // (64, 64)
    gemm_nt_bias_kahan_f32x2_kernel<<<ggrid, gblock>>>(x, W, bias, cur);

    const int vec = BATCH * C_OUT / 4;    // 262,144 float4 lanes
    lif_scan_kernel<<<vec / 256, 256>>>((const float4*)cur, (float4*)out,
                                        decay, thresh);
}